// round 6
// baseline (speedup 1.0000x reference)
#include <cuda_runtime.h>
#include <cstdint>

// Push-DIGing on GB300. N=20000, D=64, E=320000, 10 layers.
// R6: interleaved float2 (mu,my) messages -> one gather stream,
//     unroll-4 gather for MLP, warp-shfl scan fused with invd (no 25us bubble).

#define NN 20000
#define DD 64
#define EE 320000
#define NL 10
#define STEP 0.01f
#define ND (NN * DD)

__device__ float2 g_mA[ND], g_mB[ND];    // interleaved (mu, my)
__device__ float  g_mvA[NN], g_mvB[NN];
__device__ float  g_g[ND];
__device__ float  g_invd[NN];
__device__ int    g_cin[NN], g_cout[NN];
__device__ int    g_rs[NN + 1], g_pos[NN];
__device__ int    g_src[EE];

__global__ void k_cnt0() {
    int n = blockIdx.x * blockDim.x + threadIdx.x;
    if (n < NN) { g_cin[n] = 0; g_cout[n] = 0; }
}

__global__ void k_count(const int* __restrict__ ei) {
    int e = blockIdx.x * blockDim.x + threadIdx.x;
    if (e < EE) {
        atomicAdd(&g_cout[ei[e]], 1);
        atomicAdd(&g_cin[ei[e + EE]], 1);
    }
}

// Fused: exclusive scan of in-degrees -> g_rs/g_pos  AND  g_invd = 1/(1+cout).
// Single block, warp-shfl scan (2 syncthreads total).
__global__ void __launch_bounds__(1024) k_scan() {
    __shared__ int sw[32];
    int t = threadIdx.x, lane = t & 31, wid = t >> 5;
    int base = t * 20;                       // 20*1024 >= NN
    int cin[20];
    int s = 0;
#pragma unroll
    for (int q = 0; q < 5; q++) {
        int idx = base + q * 4;
        int4 c4, o4;
        if (idx + 3 < NN) {
            c4 = *(const int4*)(g_cin + idx);
            o4 = *(const int4*)(g_cout + idx);
        } else {
            c4.x = (idx + 0 < NN) ? g_cin[idx + 0] : 0;
            c4.y = (idx + 1 < NN) ? g_cin[idx + 1] : 0;
            c4.z = (idx + 2 < NN) ? g_cin[idx + 2] : 0;
            c4.w = (idx + 3 < NN) ? g_cin[idx + 3] : 0;
            o4.x = (idx + 0 < NN) ? g_cout[idx + 0] : 0;
            o4.y = (idx + 1 < NN) ? g_cout[idx + 1] : 0;
            o4.z = (idx + 2 < NN) ? g_cout[idx + 2] : 0;
            o4.w = (idx + 3 < NN) ? g_cout[idx + 3] : 0;
        }
        cin[q * 4 + 0] = c4.x; cin[q * 4 + 1] = c4.y;
        cin[q * 4 + 2] = c4.z; cin[q * 4 + 3] = c4.w;
        if (idx + 0 < NN) g_invd[idx + 0] = 1.0f / (1.0f + (float)o4.x);
        if (idx + 1 < NN) g_invd[idx + 1] = 1.0f / (1.0f + (float)o4.y);
        if (idx + 2 < NN) g_invd[idx + 2] = 1.0f / (1.0f + (float)o4.z);
        if (idx + 3 < NN) g_invd[idx + 3] = 1.0f / (1.0f + (float)o4.w);
        s += c4.x + c4.y + c4.z + c4.w;
    }
    // inclusive warp scan of per-thread totals
    int incl = s;
#pragma unroll
    for (int o = 1; o < 32; o <<= 1) {
        int v = __shfl_up_sync(0xffffffffu, incl, o);
        if (lane >= o) incl += v;
    }
    if (lane == 31) sw[wid] = incl;
    __syncthreads();
    if (wid == 0) {
        int v = sw[lane];
        int wincl = v;
#pragma unroll
        for (int o = 1; o < 32; o <<= 1) {
            int u = __shfl_up_sync(0xffffffffu, wincl, o);
            if (lane >= o) wincl += u;
        }
        sw[lane] = wincl - v;   // exclusive warp base
    }
    __syncthreads();
    int pre = sw[wid] + incl - s;           // exclusive prefix for this thread
#pragma unroll
    for (int i = 0; i < 20; i++) {
        int idx = base + i;
        if (idx < NN) { g_rs[idx] = pre; g_pos[idx] = pre; }
        pre += cin[i];
    }
    if (t == 0) g_rs[NN] = EE;
}

__global__ void k_sort(const int* __restrict__ ei) {
    int e = blockIdx.x * blockDim.x + threadIdx.x;
    if (e >= EE) return;
    int s = ei[e];
    int d = ei[e + EE];
    int p = atomicAdd(&g_pos[d], 1);
    g_src[p] = s;
}

// Fused layer kernel (one 64-thread block per node):
//   first=1 : u=xin, v=1 -> y0 = g(x); emit messages
//   first=0 : gather (mu,my)/mv over in-CSR + self; x1=u/v; g1=2Ax1+b;
//             ynew = mix(y)+g1-g[r]; g[r]=g1; emit next messages
__global__ void __launch_bounds__(64) k_fused(const float* __restrict__ A,
                                              const float* __restrict__ b,
                                              const float* __restrict__ xin,
                                              const float2* __restrict__ M,
                                              const float* __restrict__ mv,
                                              float* __restrict__ g,
                                              float2* __restrict__ Mo,
                                              float* __restrict__ mvN,
                                              int first) {
    __shared__ float4 sA[DD * 16];   // 16KB, col-swizzled c^(r&15)
    __shared__ float sx[DD];
    int d = blockIdx.x;
    int t = threadIdx.x;

    // stage A[d] via cp.async (overlaps with gather below)
    const float4* Ab = (const float4*)(A + (size_t)d * DD * DD);
#pragma unroll
    for (int k = 0; k < 16; k++) {
        int r = k * 4 + (t >> 4), c = t & 15;
        uint32_t dst = (uint32_t)__cvta_generic_to_shared(&sA[r * 16 + (c ^ (r & 15))]);
        asm volatile("cp.async.cg.shared.global [%0], [%1], 16;"
                     :: "r"(dst), "l"(Ab + k * 64 + t));
    }
    asm volatile("cp.async.commit_group;");

    float au, ayv = 0.0f, av = 1.0f;
    if (first) {
        au = __ldg(xin + d * DD + t);
    } else {
        int beg = g_rs[d], end = g_rs[d + 1];
        float2 self = M[d * DD + t];
        au = self.x; ayv = self.y; av = mv[d];
        int j = beg;
        for (; j + 4 <= end; j += 4) {
            int s0 = g_src[j], s1 = g_src[j + 1], s2 = g_src[j + 2], s3 = g_src[j + 3];
            float2 a0 = __ldg(M + s0 * DD + t);
            float2 a1 = __ldg(M + s1 * DD + t);
            float2 a2 = __ldg(M + s2 * DD + t);
            float2 a3 = __ldg(M + s3 * DD + t);
            float v0 = __ldg(mv + s0), v1 = __ldg(mv + s1);
            float v2 = __ldg(mv + s2), v3 = __ldg(mv + s3);
            au  += (a0.x + a1.x) + (a2.x + a3.x);
            ayv += (a0.y + a1.y) + (a2.y + a3.y);
            av  += (v0 + v1) + (v2 + v3);
        }
        for (; j < end; j++) {
            int s = g_src[j];
            float2 a = __ldg(M + s * DD + t);
            au += a.x; ayv += a.y; av += __ldg(mv + s);
        }
    }
    float inv = first ? 1.0f : (1.0f / av);
    sx[t] = au * inv;

    asm volatile("cp.async.wait_group 0;");
    __syncthreads();

    const float4* sx4 = (const float4*)sx;
    float acc = 0.0f;
#pragma unroll
    for (int j = 0; j < 16; j++) {
        float4 a4 = sA[t * 16 + (j ^ (t & 15))];
        float4 x4 = sx4[j];
        acc += a4.x * x4.x + a4.y * x4.y + a4.z * x4.z + a4.w * x4.w;
    }

    int r = d * DD + t;
    float gv = 2.0f * acc + __ldg(b + r);
    float ynew = first ? gv : (ayv + gv - g[r]);
    g[r] = gv;
    float w = g_invd[d];
    Mo[r] = make_float2((au - STEP * ynew) * w, ynew * w);
    if (t == 0) mvN[d] = av * w;
}

// Final layer: out = mix(u)/mix(v) only
__global__ void __launch_bounds__(64) k_final(const float2* __restrict__ M,
                                              const float* __restrict__ mv,
                                              float* __restrict__ out) {
    int d = blockIdx.x;
    int t = threadIdx.x;
    int beg = g_rs[d], end = g_rs[d + 1];
    float2 self = M[d * DD + t];
    float au = self.x;
    float av = mv[d];
    int j = beg;
    for (; j + 4 <= end; j += 4) {
        int s0 = g_src[j], s1 = g_src[j + 1], s2 = g_src[j + 2], s3 = g_src[j + 3];
        float2 a0 = __ldg(M + s0 * DD + t);
        float2 a1 = __ldg(M + s1 * DD + t);
        float2 a2 = __ldg(M + s2 * DD + t);
        float2 a3 = __ldg(M + s3 * DD + t);
        float v0 = __ldg(mv + s0), v1 = __ldg(mv + s1);
        float v2 = __ldg(mv + s2), v3 = __ldg(mv + s3);
        au += (a0.x + a1.x) + (a2.x + a3.x);
        av += (v0 + v1) + (v2 + v3);
    }
    for (; j < end; j++) {
        int s = g_src[j];
        au += __ldg(M + s * DD + t).x;
        av += __ldg(mv + s);
    }
    out[d * DD + t] = au / av;
}

__global__ void k_tail(float* o, int start, int end, float val) {
    int i = start + blockIdx.x * blockDim.x + threadIdx.x;
    if (i < end) o[i] = val;
}

extern "C" void kernel_launch(void* const* d_in, const int* in_sizes, int n_in,
                              void* d_out, int out_size) {
    const float* A = (const float*)d_in[0];
    const float* b = (const float*)d_in[1];
    const float* x = (const float*)d_in[2];
    const int* ei = (const int*)d_in[3];   // int32 (JAX x64 disabled)
    float* out = (float*)d_out;

    float2 *mA, *mB;
    float *mvA, *mvB, *g;
    cudaGetSymbolAddress((void**)&mA, g_mA);
    cudaGetSymbolAddress((void**)&mB, g_mB);
    cudaGetSymbolAddress((void**)&mvA, g_mvA);
    cudaGetSymbolAddress((void**)&mvB, g_mvB);
    cudaGetSymbolAddress((void**)&g,   g_g);

    // setup: degrees -> (invd, in-CSR) -> sorted srcs
    k_cnt0<<<(NN + 255) / 256, 256>>>();
    k_count<<<(EE + 255) / 256, 256>>>(ei);
    k_scan<<<1, 1024>>>();
    k_sort<<<(EE + 255) / 256, 256>>>(ei);

    // layer 0 prologue: y0 = grad(x); emit messages into set A
    k_fused<<<NN, 64>>>(A, b, x, nullptr, nullptr, g, mA, mvA, 1);

    // 9 full layers
    for (int L = 0; L < NL - 1; L++) {
        int p = L & 1;
        float2* m_i = p ? mB : mA;
        float*  v_i = p ? mvB : mvA;
        float2* m_o = p ? mA : mB;
        float*  v_o = p ? mvA : mvB;
        k_fused<<<NN, 64>>>(A, b, nullptr, m_i, v_i, g, m_o, v_o, 0);
    }

    // final layer: only u/v mix matters
    {
        int p = (NL - 1) & 1;
        k_final<<<NN, 64>>>(p ? mB : mA, p ? mvB : mvA, out);
    }

    if (out_size > ND) {
        float cc = (float)(3LL * NL * (long long)EE);
        int tail = out_size - ND;
        k_tail<<<(tail + 255) / 256, 256>>>(out, ND, out_size, cc);
    }
}

// round 8
// speedup vs baseline: 1.2566x; 1.2566x over previous
#include <cuda_runtime.h>
#include <cstdint>

// Push-DIGing on GB300. N=20000, D=64, E=320000, 10 layers.
// R8: R5 pull-fused structure + fused warp-shfl scan/invd + hoisted b/g loads.
//     (R7's L2 cache-policy cp.async variant trapped -> removed.)

#define NN 20000
#define DD 64
#define EE 320000
#define NL 10
#define STEP 0.01f
#define ND (NN * DD)

__device__ float g_muA[ND], g_muB[ND];
__device__ float g_myA[ND], g_myB[ND];
__device__ float g_mvA[NN], g_mvB[NN];
__device__ float g_g[ND];
__device__ float g_invd[NN];
__device__ int   g_cin[NN], g_cout[NN];
__device__ int   g_rs[NN + 1], g_pos[NN];
__device__ int   g_src[EE];

__global__ void k_cnt0() {
    int n = blockIdx.x * blockDim.x + threadIdx.x;
    if (n < NN) { g_cin[n] = 0; g_cout[n] = 0; }
}

__global__ void k_count(const int* __restrict__ ei) {
    int e = blockIdx.x * blockDim.x + threadIdx.x;
    if (e < EE) {
        atomicAdd(&g_cout[ei[e]], 1);
        atomicAdd(&g_cin[ei[e + EE]], 1);
    }
}

// Fused: exclusive scan of in-degrees -> g_rs/g_pos AND g_invd = 1/(1+cout).
// Single block, warp-shfl scan.
__global__ void __launch_bounds__(1024) k_scan() {
    __shared__ int sw[32];
    int t = threadIdx.x, lane = t & 31, wid = t >> 5;
    int base = t * 20;                       // 20*1024 >= NN
    int cin[20];
    int s = 0;
#pragma unroll
    for (int q = 0; q < 5; q++) {
        int idx = base + q * 4;
        int4 c4, o4;
        if (idx + 3 < NN) {
            c4 = *(const int4*)(g_cin + idx);
            o4 = *(const int4*)(g_cout + idx);
        } else {
            c4.x = (idx + 0 < NN) ? g_cin[idx + 0] : 0;
            c4.y = (idx + 1 < NN) ? g_cin[idx + 1] : 0;
            c4.z = (idx + 2 < NN) ? g_cin[idx + 2] : 0;
            c4.w = (idx + 3 < NN) ? g_cin[idx + 3] : 0;
            o4.x = (idx + 0 < NN) ? g_cout[idx + 0] : 0;
            o4.y = (idx + 1 < NN) ? g_cout[idx + 1] : 0;
            o4.z = (idx + 2 < NN) ? g_cout[idx + 2] : 0;
            o4.w = (idx + 3 < NN) ? g_cout[idx + 3] : 0;
        }
        cin[q * 4 + 0] = c4.x; cin[q * 4 + 1] = c4.y;
        cin[q * 4 + 2] = c4.z; cin[q * 4 + 3] = c4.w;
        if (idx + 0 < NN) g_invd[idx + 0] = 1.0f / (1.0f + (float)o4.x);
        if (idx + 1 < NN) g_invd[idx + 1] = 1.0f / (1.0f + (float)o4.y);
        if (idx + 2 < NN) g_invd[idx + 2] = 1.0f / (1.0f + (float)o4.z);
        if (idx + 3 < NN) g_invd[idx + 3] = 1.0f / (1.0f + (float)o4.w);
        s += c4.x + c4.y + c4.z + c4.w;
    }
    int incl = s;
#pragma unroll
    for (int o = 1; o < 32; o <<= 1) {
        int v = __shfl_up_sync(0xffffffffu, incl, o);
        if (lane >= o) incl += v;
    }
    if (lane == 31) sw[wid] = incl;
    __syncthreads();
    if (wid == 0) {
        int v = sw[lane];
        int wincl = v;
#pragma unroll
        for (int o = 1; o < 32; o <<= 1) {
            int u = __shfl_up_sync(0xffffffffu, wincl, o);
            if (lane >= o) wincl += u;
        }
        sw[lane] = wincl - v;
    }
    __syncthreads();
    int pre = sw[wid] + incl - s;
#pragma unroll
    for (int i = 0; i < 20; i++) {
        int idx = base + i;
        if (idx < NN) { g_rs[idx] = pre; g_pos[idx] = pre; }
        pre += cin[i];
    }
    if (t == 0) g_rs[NN] = EE;
}

__global__ void k_sort(const int* __restrict__ ei) {
    int e = blockIdx.x * blockDim.x + threadIdx.x;
    if (e >= EE) return;
    int s = ei[e];
    int d = ei[e + EE];
    int p = atomicAdd(&g_pos[d], 1);
    g_src[p] = s;
}

// Fused layer kernel (one 64-thread block per node):
//   first=1 : u=xin, v=1 -> y0 = g(x); emit messages
//   first=0 : gather mu/my/mv over in-CSR + self; x1=u/v; g1=2Ax1+b;
//             ynew = mix(y)+g1-gold; g[r]=g1; emit next messages
__global__ void __launch_bounds__(64) k_fused(const float* __restrict__ A,
                                              const float* __restrict__ b,
                                              const float* __restrict__ xin,
                                              const float* __restrict__ mu,
                                              const float* __restrict__ my,
                                              const float* __restrict__ mv,
                                              float* __restrict__ g,
                                              float* __restrict__ muN,
                                              float* __restrict__ myN,
                                              float* __restrict__ mvN,
                                              int first) {
    __shared__ float4 sA[DD * 16];   // 16KB, col-swizzled c^(r&15)
    __shared__ float sx[DD];
    int d = blockIdx.x;
    int t = threadIdx.x;

    // stage A[d] via cp.async (overlaps with gather below)
    const float4* Ab = (const float4*)(A + (size_t)d * DD * DD);
#pragma unroll
    for (int k = 0; k < 16; k++) {
        int r = k * 4 + (t >> 4), c = t & 15;
        uint32_t dst = (uint32_t)__cvta_generic_to_shared(&sA[r * 16 + (c ^ (r & 15))]);
        asm volatile("cp.async.cg.shared.global [%0], [%1], 16;"
                     :: "r"(dst), "l"(Ab + k * 64 + t));
    }
    asm volatile("cp.async.commit_group;");

    int r = d * DD + t;
    // hoist epilogue operand loads above the gather to overlap their latency
    float bv = __ldg(b + r);
    float gold = first ? 0.0f : g[r];

    float au, ayv = 0.0f, av = 1.0f;
    if (first) {
        au = __ldg(xin + r);
    } else {
        int beg = g_rs[d], end = g_rs[d + 1];
        au = mu[r];
        ayv = my[r];
        av = mv[d];
        for (int j = beg; j < end; j++) {
            int s = g_src[j];                 // broadcast load
            au  += __ldg(mu + s * DD + t);
            ayv += __ldg(my + s * DD + t);
            av  += __ldg(mv + s);             // broadcast load
        }
    }
    float inv = first ? 1.0f : (1.0f / av);
    sx[t] = au * inv;

    asm volatile("cp.async.wait_group 0;");
    __syncthreads();

    const float4* sx4 = (const float4*)sx;
    float acc = 0.0f;
#pragma unroll
    for (int j = 0; j < 16; j++) {
        float4 a4 = sA[t * 16 + (j ^ (t & 15))];
        float4 x4 = sx4[j];
        acc += a4.x * x4.x + a4.y * x4.y + a4.z * x4.z + a4.w * x4.w;
    }

    float gv = 2.0f * acc + bv;
    float ynew = first ? gv : (ayv + gv - gold);
    g[r] = gv;
    float w = g_invd[d];
    muN[r] = (au - STEP * ynew) * w;
    myN[r] = ynew * w;
    if (t == 0) mvN[d] = av * w;
}

// Final layer: out = mix(u)/mix(v) only (y path dead)
__global__ void __launch_bounds__(64) k_final(const float* __restrict__ mu,
                                              const float* __restrict__ mv,
                                              float* __restrict__ out) {
    int d = blockIdx.x;
    int t = threadIdx.x;
    int beg = g_rs[d], end = g_rs[d + 1];
    float au = mu[d * DD + t];
    float av = mv[d];
    for (int j = beg; j < end; j++) {
        int s = g_src[j];
        au += __ldg(mu + s * DD + t);
        av += __ldg(mv + s);
    }
    out[d * DD + t] = au / av;
}

__global__ void k_tail(float* o, int start, int end, float val) {
    int i = start + blockIdx.x * blockDim.x + threadIdx.x;
    if (i < end) o[i] = val;
}

extern "C" void kernel_launch(void* const* d_in, const int* in_sizes, int n_in,
                              void* d_out, int out_size) {
    const float* A = (const float*)d_in[0];
    const float* b = (const float*)d_in[1];
    const float* x = (const float*)d_in[2];
    const int* ei = (const int*)d_in[3];   // int32 (JAX x64 disabled)
    float* out = (float*)d_out;

    float *muA, *muB, *myA, *myB, *mvA, *mvB, *g;
    cudaGetSymbolAddress((void**)&muA, g_muA);
    cudaGetSymbolAddress((void**)&muB, g_muB);
    cudaGetSymbolAddress((void**)&myA, g_myA);
    cudaGetSymbolAddress((void**)&myB, g_myB);
    cudaGetSymbolAddress((void**)&mvA, g_mvA);
    cudaGetSymbolAddress((void**)&mvB, g_mvB);
    cudaGetSymbolAddress((void**)&g,   g_g);

    // setup: degrees -> (invd, in-CSR) -> sorted srcs
    k_cnt0<<<(NN + 255) / 256, 256>>>();
    k_count<<<(EE + 255) / 256, 256>>>(ei);
    k_scan<<<1, 1024>>>();
    k_sort<<<(EE + 255) / 256, 256>>>(ei);

    // layer 0 prologue: y0 = grad(x); emit messages into set A
    k_fused<<<NN, 64>>>(A, b, x, nullptr, nullptr, nullptr, g, muA, myA, mvA, 1);

    // 9 full layers
    for (int L = 0; L < NL - 1; L++) {
        int p = L & 1;
        float* mu_i = p ? muB : muA;
        float* my_i = p ? myB : myA;
        float* mv_i = p ? mvB : mvA;
        float* mu_o = p ? muA : muB;
        float* my_o = p ? myA : myB;
        float* mv_o = p ? mvA : mvB;
        k_fused<<<NN, 64>>>(A, b, nullptr, mu_i, my_i, mv_i, g, mu_o, my_o, mv_o, 0);
    }

    // final layer: only u/v mix matters
    {
        int p = (NL - 1) & 1;
        k_final<<<NN, 64>>>(p ? muB : muA, p ? mvB : mvA, out);
    }

    if (out_size > ND) {
        float cc = (float)(3LL * NL * (long long)EE);
        int tail = out_size - ND;
        k_tail<<<(tail + 255) / 256, 256>>>(out, ND, out_size, cc);
    }
}

// round 9
// speedup vs baseline: 1.5778x; 1.2556x over previous
#include <cuda_runtime.h>
#include <cuda_fp16.h>
#include <cstdint>

// Push-DIGing on GB300. N=20000, D=64, E=320000, 10 layers.
// R9: R8 structure + per-replay fp16 copy of A (halves per-layer A stream).
//     Accumulation stays fp32; only A storage is half.

#define NN 20000
#define DD 64
#define EE 320000
#define NL 10
#define STEP 0.01f
#define ND (NN * DD)
#define AELEM (ND * DD)          // 81,920,000

__device__ __half g_Ah[AELEM];   // 163.84 MB half copy of A
__device__ float g_muA[ND], g_muB[ND];
__device__ float g_myA[ND], g_myB[ND];
__device__ float g_mvA[NN], g_mvB[NN];
__device__ float g_g[ND];
__device__ float g_invd[NN];
__device__ int   g_cin[NN], g_cout[NN];
__device__ int   g_rs[NN + 1], g_pos[NN];
__device__ int   g_src[EE];

__global__ void k_cnt0() {
    int n = blockIdx.x * blockDim.x + threadIdx.x;
    if (n < NN) { g_cin[n] = 0; g_cout[n] = 0; }
}

__global__ void k_count(const int* __restrict__ ei) {
    int e = blockIdx.x * blockDim.x + threadIdx.x;
    if (e < EE) {
        atomicAdd(&g_cout[ei[e]], 1);
        atomicAdd(&g_cin[ei[e + EE]], 1);
    }
}

// A fp32 -> fp16 (8 elements per thread)
__global__ void __launch_bounds__(256) k_conv(const float4* __restrict__ A) {
    int i = blockIdx.x * blockDim.x + threadIdx.x;
    if (i >= AELEM / 8) return;
    float4 a0 = __ldg(A + 2 * i);
    float4 a1 = __ldg(A + 2 * i + 1);
    __half2 h0 = __floats2half2_rn(a0.x, a0.y);
    __half2 h1 = __floats2half2_rn(a0.z, a0.w);
    __half2 h2 = __floats2half2_rn(a1.x, a1.y);
    __half2 h3 = __floats2half2_rn(a1.z, a1.w);
    uint4 o;
    o.x = *(const unsigned*)&h0;
    o.y = *(const unsigned*)&h1;
    o.z = *(const unsigned*)&h2;
    o.w = *(const unsigned*)&h3;
    ((uint4*)g_Ah)[i] = o;
}

// Fused: exclusive scan of in-degrees -> g_rs/g_pos AND g_invd = 1/(1+cout).
__global__ void __launch_bounds__(1024) k_scan() {
    __shared__ int sw[32];
    int t = threadIdx.x, lane = t & 31, wid = t >> 5;
    int base = t * 20;
    int cin[20];
    int s = 0;
#pragma unroll
    for (int q = 0; q < 5; q++) {
        int idx = base + q * 4;
        int4 c4, o4;
        if (idx + 3 < NN) {
            c4 = *(const int4*)(g_cin + idx);
            o4 = *(const int4*)(g_cout + idx);
        } else {
            c4.x = (idx + 0 < NN) ? g_cin[idx + 0] : 0;
            c4.y = (idx + 1 < NN) ? g_cin[idx + 1] : 0;
            c4.z = (idx + 2 < NN) ? g_cin[idx + 2] : 0;
            c4.w = (idx + 3 < NN) ? g_cin[idx + 3] : 0;
            o4.x = (idx + 0 < NN) ? g_cout[idx + 0] : 0;
            o4.y = (idx + 1 < NN) ? g_cout[idx + 1] : 0;
            o4.z = (idx + 2 < NN) ? g_cout[idx + 2] : 0;
            o4.w = (idx + 3 < NN) ? g_cout[idx + 3] : 0;
        }
        cin[q * 4 + 0] = c4.x; cin[q * 4 + 1] = c4.y;
        cin[q * 4 + 2] = c4.z; cin[q * 4 + 3] = c4.w;
        if (idx + 0 < NN) g_invd[idx + 0] = 1.0f / (1.0f + (float)o4.x);
        if (idx + 1 < NN) g_invd[idx + 1] = 1.0f / (1.0f + (float)o4.y);
        if (idx + 2 < NN) g_invd[idx + 2] = 1.0f / (1.0f + (float)o4.z);
        if (idx + 3 < NN) g_invd[idx + 3] = 1.0f / (1.0f + (float)o4.w);
        s += c4.x + c4.y + c4.z + c4.w;
    }
    int incl = s;
#pragma unroll
    for (int o = 1; o < 32; o <<= 1) {
        int v = __shfl_up_sync(0xffffffffu, incl, o);
        if (lane >= o) incl += v;
    }
    if (lane == 31) sw[wid] = incl;
    __syncthreads();
    if (wid == 0) {
        int v = sw[lane];
        int wincl = v;
#pragma unroll
        for (int o = 1; o < 32; o <<= 1) {
            int u = __shfl_up_sync(0xffffffffu, wincl, o);
            if (lane >= o) wincl += u;
        }
        sw[lane] = wincl - v;
    }
    __syncthreads();
    int pre = sw[wid] + incl - s;
#pragma unroll
    for (int i = 0; i < 20; i++) {
        int idx = base + i;
        if (idx < NN) { g_rs[idx] = pre; g_pos[idx] = pre; }
        pre += cin[i];
    }
    if (t == 0) g_rs[NN] = EE;
}

__global__ void k_sort(const int* __restrict__ ei) {
    int e = blockIdx.x * blockDim.x + threadIdx.x;
    if (e >= EE) return;
    int s = ei[e];
    int d = ei[e + EE];
    int p = atomicAdd(&g_pos[d], 1);
    g_src[p] = s;
}

// Fused layer kernel (one 64-thread block per node), A in fp16:
//   first=1 : u=xin, v=1 -> y0 = g(x); emit messages
//   first=0 : gather mu/my/mv over in-CSR + self; x1=u/v; g1=2Ax1+b;
//             ynew = mix(y)+g1-gold; g[r]=g1; emit next messages
__global__ void __launch_bounds__(64) k_fused(const float* __restrict__ b,
                                              const float* __restrict__ xin,
                                              const float* __restrict__ mu,
                                              const float* __restrict__ my,
                                              const float* __restrict__ mv,
                                              float* __restrict__ g,
                                              float* __restrict__ muN,
                                              float* __restrict__ myN,
                                              float* __restrict__ mvN,
                                              int first) {
    __shared__ uint4 sAh[DD * 8];   // 8KB: row r = 8x16B granules, pos c^(r&7)
    __shared__ float sx[DD];
    int d = blockIdx.x;
    int t = threadIdx.x;

    // stage A[d] (half) via cp.async; 8 iters x 64 threads x 16B
    const uint4* Ab = (const uint4*)(g_Ah + (size_t)d * DD * DD);
#pragma unroll
    for (int k = 0; k < 8; k++) {
        int r = k * 8 + (t >> 3), c = t & 7;
        uint32_t dst = (uint32_t)__cvta_generic_to_shared(&sAh[r * 8 + (c ^ (r & 7))]);
        asm volatile("cp.async.cg.shared.global [%0], [%1], 16;"
                     :: "r"(dst), "l"(Ab + k * 64 + t));
    }
    asm volatile("cp.async.commit_group;");

    int r = d * DD + t;
    float bv = __ldg(b + r);
    float gold = first ? 0.0f : g[r];

    float au, ayv = 0.0f, av = 1.0f;
    if (first) {
        au = __ldg(xin + r);
    } else {
        int beg = g_rs[d], end = g_rs[d + 1];
        au = mu[r];
        ayv = my[r];
        av = mv[d];
        for (int j = beg; j < end; j++) {
            int s = g_src[j];
            au  += __ldg(mu + s * DD + t);
            ayv += __ldg(my + s * DD + t);
            av  += __ldg(mv + s);
        }
    }
    float inv = first ? 1.0f : (1.0f / av);
    sx[t] = au * inv;

    asm volatile("cp.async.wait_group 0;");
    __syncthreads();

    const float4* sx4 = (const float4*)sx;
    float acc = 0.0f;
#pragma unroll
    for (int j = 0; j < 8; j++) {
        uint4 raw = sAh[t * 8 + (j ^ (t & 7))];
        const __half2* hp = (const __half2*)&raw;
        float4 x0 = sx4[2 * j];
        float4 x1 = sx4[2 * j + 1];
        float2 c0 = __half22float2(hp[0]);
        float2 c1 = __half22float2(hp[1]);
        float2 c2 = __half22float2(hp[2]);
        float2 c3 = __half22float2(hp[3]);
        acc += c0.x * x0.x + c0.y * x0.y + c1.x * x0.z + c1.y * x0.w
             + c2.x * x1.x + c2.y * x1.y + c3.x * x1.z + c3.y * x1.w;
    }

    float gv = 2.0f * acc + bv;
    float ynew = first ? gv : (ayv + gv - gold);
    g[r] = gv;
    float w = g_invd[d];
    muN[r] = (au - STEP * ynew) * w;
    myN[r] = ynew * w;
    if (t == 0) mvN[d] = av * w;
}

// Final layer: out = mix(u)/mix(v) only
__global__ void __launch_bounds__(64) k_final(const float* __restrict__ mu,
                                              const float* __restrict__ mv,
                                              float* __restrict__ out) {
    int d = blockIdx.x;
    int t = threadIdx.x;
    int beg = g_rs[d], end = g_rs[d + 1];
    float au = mu[d * DD + t];
    float av = mv[d];
    for (int j = beg; j < end; j++) {
        int s = g_src[j];
        au += __ldg(mu + s * DD + t);
        av += __ldg(mv + s);
    }
    out[d * DD + t] = au / av;
}

__global__ void k_tail(float* o, int start, int end, float val) {
    int i = start + blockIdx.x * blockDim.x + threadIdx.x;
    if (i < end) o[i] = val;
}

extern "C" void kernel_launch(void* const* d_in, const int* in_sizes, int n_in,
                              void* d_out, int out_size) {
    const float* A = (const float*)d_in[0];
    const float* b = (const float*)d_in[1];
    const float* x = (const float*)d_in[2];
    const int* ei = (const int*)d_in[3];   // int32 (JAX x64 disabled)
    float* out = (float*)d_out;

    float *muA, *muB, *myA, *myB, *mvA, *mvB, *g;
    cudaGetSymbolAddress((void**)&muA, g_muA);
    cudaGetSymbolAddress((void**)&muB, g_muB);
    cudaGetSymbolAddress((void**)&myA, g_myA);
    cudaGetSymbolAddress((void**)&myB, g_myB);
    cudaGetSymbolAddress((void**)&mvA, g_mvA);
    cudaGetSymbolAddress((void**)&mvB, g_mvB);
    cudaGetSymbolAddress((void**)&g,   g_g);

    // setup: degrees -> (invd, in-CSR) -> sorted srcs ; A -> half
    k_cnt0<<<(NN + 255) / 256, 256>>>();
    k_count<<<(EE + 255) / 256, 256>>>(ei);
    k_scan<<<1, 1024>>>();
    k_sort<<<(EE + 255) / 256, 256>>>(ei);
    k_conv<<<(AELEM / 8 + 255) / 256, 256>>>((const float4*)A);

    // layer 0 prologue: y0 = grad(x); emit messages into set A
    k_fused<<<NN, 64>>>(b, x, nullptr, nullptr, nullptr, g, muA, myA, mvA, 1);

    // 9 full layers
    for (int L = 0; L < NL - 1; L++) {
        int p = L & 1;
        float* mu_i = p ? muB : muA;
        float* my_i = p ? myB : myA;
        float* mv_i = p ? mvB : mvA;
        float* mu_o = p ? muA : muB;
        float* my_o = p ? myA : myB;
        float* mv_o = p ? mvA : mvB;
        k_fused<<<NN, 64>>>(b, nullptr, mu_i, my_i, mv_i, g, mu_o, my_o, mv_o, 0);
    }

    // final layer: only u/v mix matters
    {
        int p = (NL - 1) & 1;
        k_final<<<NN, 64>>>(p ? muB : muA, p ? mvB : mvA, out);
    }

    if (out_size > ND) {
        float cc = (float)(3LL * NL * (long long)EE);
        int tail = out_size - ND;
        k_tail<<<(tail + 255) / 256, 256>>>(out, ND, out_size, cc);
    }
}

// round 10
// speedup vs baseline: 1.7350x; 1.0997x over previous
#include <cuda_runtime.h>
#include <cuda_fp16.h>
#include <cstdint>

// Push-DIGing on GB300. N=20000, D=64, E=320000, 10 layers.
// R10: R9 + A->fp16 conversion fused into the layer-0 kernel (saves a full
//      164MB pass), smem-staged src indices in the gather loop.

#define NN 20000
#define DD 64
#define EE 320000
#define NL 10
#define STEP 0.01f
#define ND (NN * DD)
#define AELEM (ND * DD)          // 81,920,000

__device__ __half g_Ah[AELEM];   // 163.84 MB half copy of A
__device__ float g_muA[ND], g_muB[ND];
__device__ float g_myA[ND], g_myB[ND];
__device__ float g_mvA[NN], g_mvB[NN];
__device__ float g_g[ND];
__device__ float g_invd[NN];
__device__ int   g_cin[NN], g_cout[NN];
__device__ int   g_rs[NN + 1], g_pos[NN];
__device__ int   g_src[EE];

__global__ void k_cnt0() {
    int n = blockIdx.x * blockDim.x + threadIdx.x;
    if (n < NN) { g_cin[n] = 0; g_cout[n] = 0; }
}

__global__ void k_count(const int* __restrict__ ei) {
    int e = blockIdx.x * blockDim.x + threadIdx.x;
    if (e < EE) {
        atomicAdd(&g_cout[ei[e]], 1);
        atomicAdd(&g_cin[ei[e + EE]], 1);
    }
}

// Fused: exclusive scan of in-degrees -> g_rs/g_pos AND g_invd = 1/(1+cout).
__global__ void __launch_bounds__(1024) k_scan() {
    __shared__ int sw[32];
    int t = threadIdx.x, lane = t & 31, wid = t >> 5;
    int base = t * 20;
    int cin[20];
    int s = 0;
#pragma unroll
    for (int q = 0; q < 5; q++) {
        int idx = base + q * 4;
        int4 c4, o4;
        if (idx + 3 < NN) {
            c4 = *(const int4*)(g_cin + idx);
            o4 = *(const int4*)(g_cout + idx);
        } else {
            c4.x = (idx + 0 < NN) ? g_cin[idx + 0] : 0;
            c4.y = (idx + 1 < NN) ? g_cin[idx + 1] : 0;
            c4.z = (idx + 2 < NN) ? g_cin[idx + 2] : 0;
            c4.w = (idx + 3 < NN) ? g_cin[idx + 3] : 0;
            o4.x = (idx + 0 < NN) ? g_cout[idx + 0] : 0;
            o4.y = (idx + 1 < NN) ? g_cout[idx + 1] : 0;
            o4.z = (idx + 2 < NN) ? g_cout[idx + 2] : 0;
            o4.w = (idx + 3 < NN) ? g_cout[idx + 3] : 0;
        }
        cin[q * 4 + 0] = c4.x; cin[q * 4 + 1] = c4.y;
        cin[q * 4 + 2] = c4.z; cin[q * 4 + 3] = c4.w;
        if (idx + 0 < NN) g_invd[idx + 0] = 1.0f / (1.0f + (float)o4.x);
        if (idx + 1 < NN) g_invd[idx + 1] = 1.0f / (1.0f + (float)o4.y);
        if (idx + 2 < NN) g_invd[idx + 2] = 1.0f / (1.0f + (float)o4.z);
        if (idx + 3 < NN) g_invd[idx + 3] = 1.0f / (1.0f + (float)o4.w);
        s += c4.x + c4.y + c4.z + c4.w;
    }
    int incl = s;
#pragma unroll
    for (int o = 1; o < 32; o <<= 1) {
        int v = __shfl_up_sync(0xffffffffu, incl, o);
        if (lane >= o) incl += v;
    }
    if (lane == 31) sw[wid] = incl;
    __syncthreads();
    if (wid == 0) {
        int v = sw[lane];
        int wincl = v;
#pragma unroll
        for (int o = 1; o < 32; o <<= 1) {
            int u = __shfl_up_sync(0xffffffffu, wincl, o);
            if (lane >= o) wincl += u;
        }
        sw[lane] = wincl - v;
    }
    __syncthreads();
    int pre = sw[wid] + incl - s;
#pragma unroll
    for (int i = 0; i < 20; i++) {
        int idx = base + i;
        if (idx < NN) { g_rs[idx] = pre; g_pos[idx] = pre; }
        pre += cin[i];
    }
    if (t == 0) g_rs[NN] = EE;
}

__global__ void k_sort(const int* __restrict__ ei) {
    int e = blockIdx.x * blockDim.x + threadIdx.x;
    if (e >= EE) return;
    int s = ei[e];
    int d = ei[e + EE];
    int p = atomicAdd(&g_pos[d], 1);
    g_src[p] = s;
}

// Layer-0 kernel: y0 = 2*A@x + b (fp32 A), emit messages, AND write fp16 A copy.
__global__ void __launch_bounds__(64) k_fused0(const float* __restrict__ A,
                                               const float* __restrict__ b,
                                               const float* __restrict__ xin,
                                               float* __restrict__ g,
                                               float* __restrict__ muN,
                                               float* __restrict__ myN,
                                               float* __restrict__ mvN) {
    __shared__ float4 sA[DD * 16];   // 16KB fp32, col-swizzled c^(r&15)
    __shared__ float sx[DD];
    int d = blockIdx.x;
    int t = threadIdx.x;

    const float4* Ab = (const float4*)(A + (size_t)d * DD * DD);
#pragma unroll
    for (int k = 0; k < 16; k++) {
        int r = k * 4 + (t >> 4), c = t & 15;
        uint32_t dst = (uint32_t)__cvta_generic_to_shared(&sA[r * 16 + (c ^ (r & 15))]);
        asm volatile("cp.async.cg.shared.global [%0], [%1], 16;"
                     :: "r"(dst), "l"(Ab + k * 64 + t));
    }
    asm volatile("cp.async.commit_group;");

    int r = d * DD + t;
    float bv = __ldg(b + r);
    float xv = __ldg(xin + r);
    sx[t] = xv;

    asm volatile("cp.async.wait_group 0;");
    __syncthreads();

    const float4* sx4 = (const float4*)sx;
    float acc = 0.0f;
#pragma unroll
    for (int j = 0; j < 16; j++) {
        float4 a4 = sA[t * 16 + (j ^ (t & 15))];
        float4 x4 = sx4[j];
        acc += a4.x * x4.x + a4.y * x4.y + a4.z * x4.z + a4.w * x4.w;
    }

    float gv = 2.0f * acc + bv;
    float ynew = gv;                 // y0 = grad(x0)
    g[r] = gv;
    float w = g_invd[d];
    muN[r] = (xv - STEP * ynew) * w;
    myN[r] = ynew * w;
    if (t == 0) mvN[d] = w;          // v0 = 1

    // epilogue: write fp16 copy of A[d] (row-major halves) for later layers
    uint4* out = (uint4*)(g_Ah + (size_t)d * DD * DD);
#pragma unroll
    for (int k = 0; k < 8; k++) {
        int idx = k * 64 + t;        // output granule: 8 halves
        int r2 = idx >> 3, q = idx & 7;
        float4 a0 = sA[r2 * 16 + ((2 * q) ^ (r2 & 15))];
        float4 a1 = sA[r2 * 16 + ((2 * q + 1) ^ (r2 & 15))];
        __half2 h0 = __floats2half2_rn(a0.x, a0.y);
        __half2 h1 = __floats2half2_rn(a0.z, a0.w);
        __half2 h2 = __floats2half2_rn(a1.x, a1.y);
        __half2 h3 = __floats2half2_rn(a1.z, a1.w);
        uint4 o;
        o.x = *(const unsigned*)&h0;
        o.y = *(const unsigned*)&h1;
        o.z = *(const unsigned*)&h2;
        o.w = *(const unsigned*)&h3;
        out[idx] = o;
    }
}

// Steady-state layer kernel (A in fp16): gather, x1=u/v, g1, y-update, emit.
__global__ void __launch_bounds__(64) k_fused(const float* __restrict__ b,
                                              const float* __restrict__ mu,
                                              const float* __restrict__ my,
                                              const float* __restrict__ mv,
                                              float* __restrict__ g,
                                              float* __restrict__ muN,
                                              float* __restrict__ myN,
                                              float* __restrict__ mvN) {
    __shared__ uint4 sAh[DD * 8];   // 8KB: row r = 8x16B granules, pos c^(r&7)
    __shared__ float sx[DD];
    __shared__ int sidx[64];
    int d = blockIdx.x;
    int t = threadIdx.x;

    const uint4* Ab = (const uint4*)(g_Ah + (size_t)d * DD * DD);
#pragma unroll
    for (int k = 0; k < 8; k++) {
        int r = k * 8 + (t >> 3), c = t & 7;
        uint32_t dst = (uint32_t)__cvta_generic_to_shared(&sAh[r * 8 + (c ^ (r & 7))]);
        asm volatile("cp.async.cg.shared.global [%0], [%1], 16;"
                     :: "r"(dst), "l"(Ab + k * 64 + t));
    }
    asm volatile("cp.async.commit_group;");

    int r = d * DD + t;
    float bv = __ldg(b + r);
    float gold = g[r];

    int beg = g_rs[d], end = g_rs[d + 1];
    float au = mu[r];
    float ayv = my[r];
    float av = mv[d];
    for (int base = beg; base < end; base += 64) {
        int m = end - base; if (m > 64) m = 64;
        __syncthreads();
        if (t < m) sidx[t] = g_src[base + t];
        __syncthreads();
        for (int j = 0; j < m; j++) {
            int s = sidx[j];
            au  += __ldg(mu + s * DD + t);
            ayv += __ldg(my + s * DD + t);
            av  += __ldg(mv + s);
        }
    }
    float inv = 1.0f / av;
    __syncthreads();              // sidx/sx reuse safety
    sx[t] = au * inv;

    asm volatile("cp.async.wait_group 0;");
    __syncthreads();

    const float4* sx4 = (const float4*)sx;
    float acc = 0.0f;
#pragma unroll
    for (int j = 0; j < 8; j++) {
        uint4 raw = sAh[t * 8 + (j ^ (t & 7))];
        const __half2* hp = (const __half2*)&raw;
        float4 x0 = sx4[2 * j];
        float4 x1 = sx4[2 * j + 1];
        float2 c0 = __half22float2(hp[0]);
        float2 c1 = __half22float2(hp[1]);
        float2 c2 = __half22float2(hp[2]);
        float2 c3 = __half22float2(hp[3]);
        acc += c0.x * x0.x + c0.y * x0.y + c1.x * x0.z + c1.y * x0.w
             + c2.x * x1.x + c2.y * x1.y + c3.x * x1.z + c3.y * x1.w;
    }

    float gv = 2.0f * acc + bv;
    float ynew = ayv + gv - gold;
    g[r] = gv;
    float w = g_invd[d];
    muN[r] = (au - STEP * ynew) * w;
    myN[r] = ynew * w;
    if (t == 0) mvN[d] = av * w;
}

// Final layer: out = mix(u)/mix(v) only
__global__ void __launch_bounds__(64) k_final(const float* __restrict__ mu,
                                              const float* __restrict__ mv,
                                              float* __restrict__ out) {
    int d = blockIdx.x;
    int t = threadIdx.x;
    int beg = g_rs[d], end = g_rs[d + 1];
    float au = mu[d * DD + t];
    float av = mv[d];
    for (int j = beg; j < end; j++) {
        int s = g_src[j];
        au += __ldg(mu + s * DD + t);
        av += __ldg(mv + s);
    }
    out[d * DD + t] = au / av;
}

__global__ void k_tail(float* o, int start, int end, float val) {
    int i = start + blockIdx.x * blockDim.x + threadIdx.x;
    if (i < end) o[i] = val;
}

extern "C" void kernel_launch(void* const* d_in, const int* in_sizes, int n_in,
                              void* d_out, int out_size) {
    const float* A = (const float*)d_in[0];
    const float* b = (const float*)d_in[1];
    const float* x = (const float*)d_in[2];
    const int* ei = (const int*)d_in[3];   // int32 (JAX x64 disabled)
    float* out = (float*)d_out;

    float *muA, *muB, *myA, *myB, *mvA, *mvB, *g;
    cudaGetSymbolAddress((void**)&muA, g_muA);
    cudaGetSymbolAddress((void**)&muB, g_muB);
    cudaGetSymbolAddress((void**)&myA, g_myA);
    cudaGetSymbolAddress((void**)&myB, g_myB);
    cudaGetSymbolAddress((void**)&mvA, g_mvA);
    cudaGetSymbolAddress((void**)&mvB, g_mvB);
    cudaGetSymbolAddress((void**)&g,   g_g);

    // setup: degrees -> (invd, in-CSR) -> sorted srcs
    k_cnt0<<<(NN + 255) / 256, 256>>>();
    k_count<<<(EE + 255) / 256, 256>>>(ei);
    k_scan<<<1, 1024>>>();
    k_sort<<<(EE + 255) / 256, 256>>>(ei);

    // layer 0: fp32 A matvec + emit messages + write fp16 A copy
    k_fused0<<<NN, 64>>>(A, b, x, g, muA, myA, mvA);

    // 9 steady-state layers
    for (int L = 0; L < NL - 1; L++) {
        int p = L & 1;
        float* mu_i = p ? muB : muA;
        float* my_i = p ? myB : myA;
        float* mv_i = p ? mvB : mvA;
        float* mu_o = p ? muA : muB;
        float* my_o = p ? myA : myB;
        float* mv_o = p ? mvA : mvB;
        k_fused<<<NN, 64>>>(b, mu_i, my_i, mv_i, g, mu_o, my_o, mv_o);
    }

    // final layer: only u/v mix matters
    {
        int p = (NL - 1) & 1;
        k_final<<<NN, 64>>>(p ? muB : muA, p ? mvB : mvA, out);
    }

    if (out_size > ND) {
        float cc = (float)(3LL * NL * (long long)EE);
        int tail = out_size - ND;
        k_tail<<<(tail + 255) / 256, 256>>>(out, ND, out_size, cc);
    }
}

// round 11
// speedup vs baseline: 1.7901x; 1.0317x over previous
#include <cuda_runtime.h>
#include <cuda_fp16.h>
#include <cstdint>

// Push-DIGing on GB300. N=20000, D=64, E=320000, 10 layers.
// R11: R10 + packed half2 (mu,my) messages -> gather traffic halved.
//      Last steady layer also emits fp32 mu so the final mix is unquantized.

#define NN 20000
#define DD 64
#define EE 320000
#define NL 10
#define STEP 0.01f
#define ND (NN * DD)
#define AELEM (ND * DD)          // 81,920,000

__device__ __half  g_Ah[AELEM];  // 163.84 MB half copy of A
__device__ __half2 g_MA[ND], g_MB[ND];   // packed (mu, my) messages
__device__ float g_muF[ND];              // fp32 mu for the final mix
__device__ float g_mvA[NN], g_mvB[NN];
__device__ float g_g[ND];
__device__ float g_invd[NN];
__device__ int   g_cin[NN], g_cout[NN];
__device__ int   g_rs[NN + 1], g_pos[NN];
__device__ int   g_src[EE];

__global__ void k_cnt0() {
    int n = blockIdx.x * blockDim.x + threadIdx.x;
    if (n < NN) { g_cin[n] = 0; g_cout[n] = 0; }
}

__global__ void k_count(const int* __restrict__ ei) {
    int e = blockIdx.x * blockDim.x + threadIdx.x;
    if (e < EE) {
        atomicAdd(&g_cout[ei[e]], 1);
        atomicAdd(&g_cin[ei[e + EE]], 1);
    }
}

// Fused: exclusive scan of in-degrees -> g_rs/g_pos AND g_invd = 1/(1+cout).
__global__ void __launch_bounds__(1024) k_scan() {
    __shared__ int sw[32];
    int t = threadIdx.x, lane = t & 31, wid = t >> 5;
    int base = t * 20;
    int cin[20];
    int s = 0;
#pragma unroll
    for (int q = 0; q < 5; q++) {
        int idx = base + q * 4;
        int4 c4, o4;
        if (idx + 3 < NN) {
            c4 = *(const int4*)(g_cin + idx);
            o4 = *(const int4*)(g_cout + idx);
        } else {
            c4.x = (idx + 0 < NN) ? g_cin[idx + 0] : 0;
            c4.y = (idx + 1 < NN) ? g_cin[idx + 1] : 0;
            c4.z = (idx + 2 < NN) ? g_cin[idx + 2] : 0;
            c4.w = (idx + 3 < NN) ? g_cin[idx + 3] : 0;
            o4.x = (idx + 0 < NN) ? g_cout[idx + 0] : 0;
            o4.y = (idx + 1 < NN) ? g_cout[idx + 1] : 0;
            o4.z = (idx + 2 < NN) ? g_cout[idx + 2] : 0;
            o4.w = (idx + 3 < NN) ? g_cout[idx + 3] : 0;
        }
        cin[q * 4 + 0] = c4.x; cin[q * 4 + 1] = c4.y;
        cin[q * 4 + 2] = c4.z; cin[q * 4 + 3] = c4.w;
        if (idx + 0 < NN) g_invd[idx + 0] = 1.0f / (1.0f + (float)o4.x);
        if (idx + 1 < NN) g_invd[idx + 1] = 1.0f / (1.0f + (float)o4.y);
        if (idx + 2 < NN) g_invd[idx + 2] = 1.0f / (1.0f + (float)o4.z);
        if (idx + 3 < NN) g_invd[idx + 3] = 1.0f / (1.0f + (float)o4.w);
        s += c4.x + c4.y + c4.z + c4.w;
    }
    int incl = s;
#pragma unroll
    for (int o = 1; o < 32; o <<= 1) {
        int v = __shfl_up_sync(0xffffffffu, incl, o);
        if (lane >= o) incl += v;
    }
    if (lane == 31) sw[wid] = incl;
    __syncthreads();
    if (wid == 0) {
        int v = sw[lane];
        int wincl = v;
#pragma unroll
        for (int o = 1; o < 32; o <<= 1) {
            int u = __shfl_up_sync(0xffffffffu, wincl, o);
            if (lane >= o) wincl += u;
        }
        sw[lane] = wincl - v;
    }
    __syncthreads();
    int pre = sw[wid] + incl - s;
#pragma unroll
    for (int i = 0; i < 20; i++) {
        int idx = base + i;
        if (idx < NN) { g_rs[idx] = pre; g_pos[idx] = pre; }
        pre += cin[i];
    }
    if (t == 0) g_rs[NN] = EE;
}

__global__ void k_sort(const int* __restrict__ ei) {
    int e = blockIdx.x * blockDim.x + threadIdx.x;
    if (e >= EE) return;
    int s = ei[e];
    int d = ei[e + EE];
    int p = atomicAdd(&g_pos[d], 1);
    g_src[p] = s;
}

// Layer-0: y0 = 2*A@x + b (fp32 A), emit half2 messages, write fp16 A copy.
__global__ void __launch_bounds__(64) k_fused0(const float* __restrict__ A,
                                               const float* __restrict__ b,
                                               const float* __restrict__ xin,
                                               float* __restrict__ g,
                                               __half2* __restrict__ Mo,
                                               float* __restrict__ mvN) {
    __shared__ float4 sA[DD * 16];   // 16KB fp32, col-swizzled c^(r&15)
    __shared__ float sx[DD];
    int d = blockIdx.x;
    int t = threadIdx.x;

    const float4* Ab = (const float4*)(A + (size_t)d * DD * DD);
#pragma unroll
    for (int k = 0; k < 16; k++) {
        int r = k * 4 + (t >> 4), c = t & 15;
        uint32_t dst = (uint32_t)__cvta_generic_to_shared(&sA[r * 16 + (c ^ (r & 15))]);
        asm volatile("cp.async.cg.shared.global [%0], [%1], 16;"
                     :: "r"(dst), "l"(Ab + k * 64 + t));
    }
    asm volatile("cp.async.commit_group;");

    int r = d * DD + t;
    float bv = __ldg(b + r);
    float xv = __ldg(xin + r);
    sx[t] = xv;

    asm volatile("cp.async.wait_group 0;");
    __syncthreads();

    const float4* sx4 = (const float4*)sx;
    float acc = 0.0f;
#pragma unroll
    for (int j = 0; j < 16; j++) {
        float4 a4 = sA[t * 16 + (j ^ (t & 15))];
        float4 x4 = sx4[j];
        acc += a4.x * x4.x + a4.y * x4.y + a4.z * x4.z + a4.w * x4.w;
    }

    float gv = 2.0f * acc + bv;
    float ynew = gv;                 // y0 = grad(x0)
    g[r] = gv;
    float w = g_invd[d];
    Mo[r] = __floats2half2_rn((xv - STEP * ynew) * w, ynew * w);
    if (t == 0) mvN[d] = w;          // v0 = 1

    // epilogue: write fp16 copy of A[d] for later layers
    uint4* outh = (uint4*)(g_Ah + (size_t)d * DD * DD);
#pragma unroll
    for (int k = 0; k < 8; k++) {
        int idx = k * 64 + t;        // output granule: 8 halves
        int r2 = idx >> 3, q = idx & 7;
        float4 a0 = sA[r2 * 16 + ((2 * q) ^ (r2 & 15))];
        float4 a1 = sA[r2 * 16 + ((2 * q + 1) ^ (r2 & 15))];
        __half2 h0 = __floats2half2_rn(a0.x, a0.y);
        __half2 h1 = __floats2half2_rn(a0.z, a0.w);
        __half2 h2 = __floats2half2_rn(a1.x, a1.y);
        __half2 h3 = __floats2half2_rn(a1.z, a1.w);
        uint4 o;
        o.x = *(const unsigned*)&h0;
        o.y = *(const unsigned*)&h1;
        o.z = *(const unsigned*)&h2;
        o.w = *(const unsigned*)&h3;
        outh[idx] = o;
    }
}

// Steady-state layer (A fp16, messages half2): gather, x1=u/v, g1, y-update, emit.
// muF (nullable): also emit fp32 mu for the final mix.
__global__ void __launch_bounds__(64) k_fused(const float* __restrict__ b,
                                              const __half2* __restrict__ M,
                                              const float* __restrict__ mv,
                                              float* __restrict__ g,
                                              __half2* __restrict__ Mo,
                                              float* __restrict__ mvN,
                                              float* __restrict__ muF) {
    __shared__ uint4 sAh[DD * 8];   // 8KB fp16 A, pos c^(r&7)
    __shared__ float sx[DD];
    __shared__ int sidx[64];
    int d = blockIdx.x;
    int t = threadIdx.x;

    const uint4* Ab = (const uint4*)(g_Ah + (size_t)d * DD * DD);
#pragma unroll
    for (int k = 0; k < 8; k++) {
        int r = k * 8 + (t >> 3), c = t & 7;
        uint32_t dst = (uint32_t)__cvta_generic_to_shared(&sAh[r * 8 + (c ^ (r & 7))]);
        asm volatile("cp.async.cg.shared.global [%0], [%1], 16;"
                     :: "r"(dst), "l"(Ab + k * 64 + t));
    }
    asm volatile("cp.async.commit_group;");

    int r = d * DD + t;
    float bv = __ldg(b + r);
    float gold = g[r];

    int beg = g_rs[d], end = g_rs[d + 1];
    float2 self = __half22float2(M[r]);
    float au = self.x;
    float ayv = self.y;
    float av = mv[d];
    for (int base = beg; base < end; base += 64) {
        int m = end - base; if (m > 64) m = 64;
        __syncthreads();
        if (t < m) sidx[t] = g_src[base + t];
        __syncthreads();
        for (int j = 0; j < m; j++) {
            int s = sidx[j];
            float2 f = __half22float2(__ldg(M + s * DD + t));
            au  += f.x;
            ayv += f.y;
            av  += __ldg(mv + s);
        }
    }
    float inv = 1.0f / av;
    __syncthreads();
    sx[t] = au * inv;

    asm volatile("cp.async.wait_group 0;");
    __syncthreads();

    const float4* sx4 = (const float4*)sx;
    float acc = 0.0f;
#pragma unroll
    for (int j = 0; j < 8; j++) {
        uint4 raw = sAh[t * 8 + (j ^ (t & 7))];
        const __half2* hp = (const __half2*)&raw;
        float4 x0 = sx4[2 * j];
        float4 x1 = sx4[2 * j + 1];
        float2 c0 = __half22float2(hp[0]);
        float2 c1 = __half22float2(hp[1]);
        float2 c2 = __half22float2(hp[2]);
        float2 c3 = __half22float2(hp[3]);
        acc += c0.x * x0.x + c0.y * x0.y + c1.x * x0.z + c1.y * x0.w
             + c2.x * x1.x + c2.y * x1.y + c3.x * x1.z + c3.y * x1.w;
    }

    float gv = 2.0f * acc + bv;
    float ynew = ayv + gv - gold;
    g[r] = gv;
    float w = g_invd[d];
    float munew = (au - STEP * ynew) * w;
    Mo[r] = __floats2half2_rn(munew, ynew * w);
    if (muF) muF[r] = munew;          // exact mu for the final mix
    if (t == 0) mvN[d] = av * w;
}

// Final layer: out = mix(u)/mix(v), fp32 mu inputs
__global__ void __launch_bounds__(64) k_final(const float* __restrict__ mu,
                                              const float* __restrict__ mv,
                                              float* __restrict__ out) {
    int d = blockIdx.x;
    int t = threadIdx.x;
    int beg = g_rs[d], end = g_rs[d + 1];
    float au = mu[d * DD + t];
    float av = mv[d];
    for (int j = beg; j < end; j++) {
        int s = g_src[j];
        au += __ldg(mu + s * DD + t);
        av += __ldg(mv + s);
    }
    out[d * DD + t] = au / av;
}

__global__ void k_tail(float* o, int start, int end, float val) {
    int i = start + blockIdx.x * blockDim.x + threadIdx.x;
    if (i < end) o[i] = val;
}

extern "C" void kernel_launch(void* const* d_in, const int* in_sizes, int n_in,
                              void* d_out, int out_size) {
    const float* A = (const float*)d_in[0];
    const float* b = (const float*)d_in[1];
    const float* x = (const float*)d_in[2];
    const int* ei = (const int*)d_in[3];   // int32 (JAX x64 disabled)
    float* out = (float*)d_out;

    __half2 *MA, *MB;
    float *mvA, *mvB, *g, *muF;
    cudaGetSymbolAddress((void**)&MA, g_MA);
    cudaGetSymbolAddress((void**)&MB, g_MB);
    cudaGetSymbolAddress((void**)&mvA, g_mvA);
    cudaGetSymbolAddress((void**)&mvB, g_mvB);
    cudaGetSymbolAddress((void**)&g,   g_g);
    cudaGetSymbolAddress((void**)&muF, g_muF);

    // setup: degrees -> (invd, in-CSR) -> sorted srcs
    k_cnt0<<<(NN + 255) / 256, 256>>>();
    k_count<<<(EE + 255) / 256, 256>>>(ei);
    k_scan<<<1, 1024>>>();
    k_sort<<<(EE + 255) / 256, 256>>>(ei);

    // layer 0: fp32 A matvec + emit messages + write fp16 A copy
    k_fused0<<<NN, 64>>>(A, b, x, g, MA, mvA);

    // 9 steady-state layers; last one also emits fp32 mu for the final mix
    for (int L = 0; L < NL - 1; L++) {
        int p = L & 1;
        __half2* m_i = p ? MB : MA;
        float*   v_i = p ? mvB : mvA;
        __half2* m_o = p ? MA : MB;
        float*   v_o = p ? mvA : mvB;
        float* muFp = (L == NL - 2) ? muF : nullptr;
        k_fused<<<NN, 64>>>(b, m_i, v_i, g, m_o, v_o, muFp);
    }

    // final layer: only u/v mix matters (fp32 mu)
    {
        int p = (NL - 1) & 1;
        k_final<<<NN, 64>>>(muF, p ? mvB : mvA, out);
    }

    if (out_size > ND) {
        float cc = (float)(3LL * NL * (long long)EE);
        int tail = out_size - ND;
        k_tail<<<(tail + 255) / 256, 256>>>(out, ND, out_size, cc);
    }
}

// round 12
// speedup vs baseline: 2.0473x; 1.1437x over previous
#include <cuda_runtime.h>
#include <cuda_fp16.h>
#include <cstdint>

// Push-DIGing on GB300. N=20000, D=64, E=320000, 10 layers.
// R12: A stored int8 + per-row fp32 scale (82MB -> L2-resident across layers).
//      Layer 0 computes in fp32 and quantizes A in its epilogue.
//      Messages stay packed half2; final mix uses fp32 mu.

#define NN 20000
#define DD 64
#define EE 320000
#define NL 10
#define STEP 0.01f
#define ND (NN * DD)
#define AELEM (ND * DD)          // 81,920,000

__device__ int8_t  g_Ai[AELEM];  // 81.9 MB int8 A
__device__ float   g_As[ND];     // per-row scales
__device__ __half2 g_MA[ND], g_MB[ND];   // packed (mu, my) messages
__device__ float g_muF[ND];              // fp32 mu for the final mix
__device__ float g_mvA[NN], g_mvB[NN];
__device__ float g_g[ND];
__device__ float g_invd[NN];
__device__ int   g_cin[NN], g_cout[NN];
__device__ int   g_rs[NN + 1], g_pos[NN];
__device__ int   g_src[EE];

__global__ void k_cnt0() {
    int n = blockIdx.x * blockDim.x + threadIdx.x;
    if (n < NN) { g_cin[n] = 0; g_cout[n] = 0; }
}

__global__ void k_count(const int* __restrict__ ei) {
    int e = blockIdx.x * blockDim.x + threadIdx.x;
    if (e < EE) {
        atomicAdd(&g_cout[ei[e]], 1);
        atomicAdd(&g_cin[ei[e + EE]], 1);
    }
}

// Fused: exclusive scan of in-degrees -> g_rs/g_pos AND g_invd = 1/(1+cout).
__global__ void __launch_bounds__(1024) k_scan() {
    __shared__ int sw[32];
    int t = threadIdx.x, lane = t & 31, wid = t >> 5;
    int base = t * 20;
    int cin[20];
    int s = 0;
#pragma unroll
    for (int q = 0; q < 5; q++) {
        int idx = base + q * 4;
        int4 c4, o4;
        if (idx + 3 < NN) {
            c4 = *(const int4*)(g_cin + idx);
            o4 = *(const int4*)(g_cout + idx);
        } else {
            c4.x = (idx + 0 < NN) ? g_cin[idx + 0] : 0;
            c4.y = (idx + 1 < NN) ? g_cin[idx + 1] : 0;
            c4.z = (idx + 2 < NN) ? g_cin[idx + 2] : 0;
            c4.w = (idx + 3 < NN) ? g_cin[idx + 3] : 0;
            o4.x = (idx + 0 < NN) ? g_cout[idx + 0] : 0;
            o4.y = (idx + 1 < NN) ? g_cout[idx + 1] : 0;
            o4.z = (idx + 2 < NN) ? g_cout[idx + 2] : 0;
            o4.w = (idx + 3 < NN) ? g_cout[idx + 3] : 0;
        }
        cin[q * 4 + 0] = c4.x; cin[q * 4 + 1] = c4.y;
        cin[q * 4 + 2] = c4.z; cin[q * 4 + 3] = c4.w;
        if (idx + 0 < NN) g_invd[idx + 0] = 1.0f / (1.0f + (float)o4.x);
        if (idx + 1 < NN) g_invd[idx + 1] = 1.0f / (1.0f + (float)o4.y);
        if (idx + 2 < NN) g_invd[idx + 2] = 1.0f / (1.0f + (float)o4.z);
        if (idx + 3 < NN) g_invd[idx + 3] = 1.0f / (1.0f + (float)o4.w);
        s += c4.x + c4.y + c4.z + c4.w;
    }
    int incl = s;
#pragma unroll
    for (int o = 1; o < 32; o <<= 1) {
        int v = __shfl_up_sync(0xffffffffu, incl, o);
        if (lane >= o) incl += v;
    }
    if (lane == 31) sw[wid] = incl;
    __syncthreads();
    if (wid == 0) {
        int v = sw[lane];
        int wincl = v;
#pragma unroll
        for (int o = 1; o < 32; o <<= 1) {
            int u = __shfl_up_sync(0xffffffffu, wincl, o);
            if (lane >= o) wincl += u;
        }
        sw[lane] = wincl - v;
    }
    __syncthreads();
    int pre = sw[wid] + incl - s;
#pragma unroll
    for (int i = 0; i < 20; i++) {
        int idx = base + i;
        if (idx < NN) { g_rs[idx] = pre; g_pos[idx] = pre; }
        pre += cin[i];
    }
    if (t == 0) g_rs[NN] = EE;
}

__global__ void k_sort(const int* __restrict__ ei) {
    int e = blockIdx.x * blockDim.x + threadIdx.x;
    if (e >= EE) return;
    int s = ei[e];
    int d = ei[e + EE];
    int p = atomicAdd(&g_pos[d], 1);
    g_src[p] = s;
}

// Layer-0: y0 = 2*A@x + b (fp32 A), emit half2 messages, write int8 A + scales.
__global__ void __launch_bounds__(64) k_fused0(const float* __restrict__ A,
                                               const float* __restrict__ b,
                                               const float* __restrict__ xin,
                                               float* __restrict__ g,
                                               __half2* __restrict__ Mo,
                                               float* __restrict__ mvN) {
    __shared__ float4 sA[DD * 16];   // 16KB fp32, col-swizzled c^(r&15)
    __shared__ float sx[DD];
    int d = blockIdx.x;
    int t = threadIdx.x;

    const float4* Ab = (const float4*)(A + (size_t)d * DD * DD);
#pragma unroll
    for (int k = 0; k < 16; k++) {
        int r = k * 4 + (t >> 4), c = t & 15;
        uint32_t dst = (uint32_t)__cvta_generic_to_shared(&sA[r * 16 + (c ^ (r & 15))]);
        asm volatile("cp.async.cg.shared.global [%0], [%1], 16;"
                     :: "r"(dst), "l"(Ab + k * 64 + t));
    }
    asm volatile("cp.async.commit_group;");

    int r = d * DD + t;
    float bv = __ldg(b + r);
    float xv = __ldg(xin + r);
    sx[t] = xv;

    asm volatile("cp.async.wait_group 0;");
    __syncthreads();

    const float4* sx4 = (const float4*)sx;
    float acc = 0.0f;
    float amax = 0.0f;
#pragma unroll
    for (int j = 0; j < 16; j++) {
        float4 a4 = sA[t * 16 + (j ^ (t & 15))];
        float4 x4 = sx4[j];
        acc += a4.x * x4.x + a4.y * x4.y + a4.z * x4.z + a4.w * x4.w;
        amax = fmaxf(amax, fmaxf(fmaxf(fabsf(a4.x), fabsf(a4.y)),
                                 fmaxf(fabsf(a4.z), fabsf(a4.w))));
    }

    float gv = 2.0f * acc + bv;
    float ynew = gv;                 // y0 = grad(x0)
    g[r] = gv;
    float w = g_invd[d];
    Mo[r] = __floats2half2_rn((xv - STEP * ynew) * w, ynew * w);
    if (t == 0) mvN[d] = w;          // v0 = 1

    // epilogue: quantize row t of A[d] to int8 with per-row scale
    float scale = amax * (1.0f / 127.0f);
    float invs = (amax > 0.0f) ? (127.0f / amax) : 0.0f;
    g_As[r] = scale;
    uint4* Aout = (uint4*)(g_Ai + (size_t)d * DD * DD + t * DD);
#pragma unroll
    for (int jj = 0; jj < 4; jj++) {
        unsigned words[4];
#pragma unroll
        for (int m = 0; m < 4; m++) {
            int j = jj * 4 + m;
            float4 a4 = sA[t * 16 + (j ^ (t & 15))];
            int q0 = __float2int_rn(a4.x * invs);
            int q1 = __float2int_rn(a4.y * invs);
            int q2 = __float2int_rn(a4.z * invs);
            int q3 = __float2int_rn(a4.w * invs);
            words[m] = (q0 & 255) | ((q1 & 255) << 8) | ((q2 & 255) << 16)
                     | ((unsigned)(q3 & 255) << 24);
        }
        uint4 o; o.x = words[0]; o.y = words[1]; o.z = words[2]; o.w = words[3];
        Aout[jj] = o;
    }
}

// Steady-state layer (A int8, messages half2): gather, x1=u/v, g1, y-update, emit.
// muF (nullable): also emit fp32 mu for the final mix.
__global__ void __launch_bounds__(64) k_fused(const float* __restrict__ b,
                                              const __half2* __restrict__ M,
                                              const float* __restrict__ mv,
                                              float* __restrict__ g,
                                              __half2* __restrict__ Mo,
                                              float* __restrict__ mvN,
                                              float* __restrict__ muF) {
    __shared__ uint4 sAi[DD * 5];   // 5120B: row r = 4 granules @ stride 5 (conflict-free)
    __shared__ float sx[DD];
    __shared__ int sidx[64];
    int d = blockIdx.x;
    int t = threadIdx.x;

    const uint4* Ab = (const uint4*)(g_Ai + (size_t)d * DD * DD);
#pragma unroll
    for (int k = 0; k < 4; k++) {
        int idx = k * 64 + t;
        int r = idx >> 2, c = idx & 3;
        uint32_t dst = (uint32_t)__cvta_generic_to_shared(&sAi[r * 5 + c]);
        asm volatile("cp.async.cg.shared.global [%0], [%1], 16;"
                     :: "r"(dst), "l"(Ab + idx));
    }
    asm volatile("cp.async.commit_group;");

    int r = d * DD + t;
    float bv = __ldg(b + r);
    float gold = g[r];
    float scale = __ldg(g_As + r);

    int beg = g_rs[d], end = g_rs[d + 1];
    float2 self = __half22float2(M[r]);
    float au = self.x;
    float ayv = self.y;
    float av = mv[d];
    for (int base = beg; base < end; base += 64) {
        int m = end - base; if (m > 64) m = 64;
        __syncthreads();
        if (t < m) sidx[t] = g_src[base + t];
        __syncthreads();
        for (int j = 0; j < m; j++) {
            int s = sidx[j];
            float2 f = __half22float2(__ldg(M + s * DD + t));
            au  += f.x;
            ayv += f.y;
            av  += __ldg(mv + s);
        }
    }
    float inv = 1.0f / av;
    __syncthreads();
    sx[t] = au * inv;

    asm volatile("cp.async.wait_group 0;");
    __syncthreads();

    const float4* sx4 = (const float4*)sx;
    float acc = 0.0f;
#pragma unroll
    for (int q = 0; q < 4; q++) {
        uint4 w4 = sAi[t * 5 + q];
        unsigned ws[4] = {w4.x, w4.y, w4.z, w4.w};
#pragma unroll
        for (int m = 0; m < 4; m++) {
            unsigned w = ws[m];
            float4 x4 = sx4[q * 4 + m];
            float f0 = (float)((int)(w << 24) >> 24);
            float f1 = (float)((int)(w << 16) >> 24);
            float f2 = (float)((int)(w <<  8) >> 24);
            float f3 = (float)((int)w >> 24);
            acc += f0 * x4.x + f1 * x4.y + f2 * x4.z + f3 * x4.w;
        }
    }

    float gv = 2.0f * scale * acc + bv;
    float ynew = ayv + gv - gold;
    g[r] = gv;
    float w = g_invd[d];
    float munew = (au - STEP * ynew) * w;
    Mo[r] = __floats2half2_rn(munew, ynew * w);
    if (muF) muF[r] = munew;          // exact mu for the final mix
    if (t == 0) mvN[d] = av * w;
}

// Final layer: out = mix(u)/mix(v), fp32 mu inputs
__global__ void __launch_bounds__(64) k_final(const float* __restrict__ mu,
                                              const float* __restrict__ mv,
                                              float* __restrict__ out) {
    int d = blockIdx.x;
    int t = threadIdx.x;
    int beg = g_rs[d], end = g_rs[d + 1];
    float au = mu[d * DD + t];
    float av = mv[d];
    for (int j = beg; j < end; j++) {
        int s = g_src[j];
        au += __ldg(mu + s * DD + t);
        av += __ldg(mv + s);
    }
    out[d * DD + t] = au / av;
}

__global__ void k_tail(float* o, int start, int end, float val) {
    int i = start + blockIdx.x * blockDim.x + threadIdx.x;
    if (i < end) o[i] = val;
}

extern "C" void kernel_launch(void* const* d_in, const int* in_sizes, int n_in,
                              void* d_out, int out_size) {
    const float* A = (const float*)d_in[0];
    const float* b = (const float*)d_in[1];
    const float* x = (const float*)d_in[2];
    const int* ei = (const int*)d_in[3];   // int32 (JAX x64 disabled)
    float* out = (float*)d_out;

    __half2 *MA, *MB;
    float *mvA, *mvB, *g, *muF;
    cudaGetSymbolAddress((void**)&MA, g_MA);
    cudaGetSymbolAddress((void**)&MB, g_MB);
    cudaGetSymbolAddress((void**)&mvA, g_mvA);
    cudaGetSymbolAddress((void**)&mvB, g_mvB);
    cudaGetSymbolAddress((void**)&g,   g_g);
    cudaGetSymbolAddress((void**)&muF, g_muF);

    // setup: degrees -> (invd, in-CSR) -> sorted srcs
    k_cnt0<<<(NN + 255) / 256, 256>>>();
    k_count<<<(EE + 255) / 256, 256>>>(ei);
    k_scan<<<1, 1024>>>();
    k_sort<<<(EE + 255) / 256, 256>>>(ei);

    // layer 0: fp32 A matvec + emit messages + write int8 A copy + scales
    k_fused0<<<NN, 64>>>(A, b, x, g, MA, mvA);

    // 9 steady-state layers; last one also emits fp32 mu for the final mix
    for (int L = 0; L < NL - 1; L++) {
        int p = L & 1;
        __half2* m_i = p ? MB : MA;
        float*   v_i = p ? mvB : mvA;
        __half2* m_o = p ? MA : MB;
        float*   v_o = p ? mvA : mvB;
        float* muFp = (L == NL - 2) ? muF : nullptr;
        k_fused<<<NN, 64>>>(b, m_i, v_i, g, m_o, v_o, muFp);
    }

    // final layer: only u/v mix matters (fp32 mu)
    {
        int p = (NL - 1) & 1;
        k_final<<<NN, 64>>>(muF, p ? mvB : mvA, out);
    }

    if (out_size > ND) {
        float cc = (float)(3LL * NL * (long long)EE);
        int tail = out_size - ND;
        k_tail<<<(tail + 255) / 256, 256>>>(out, ND, out_size, cc);
    }
}